// round 1
// baseline (speedup 1.0000x reference)
#include <cuda_runtime.h>
#include <math.h>

// ---------------------------------------------------------------------------
// Problem dims
// ---------------------------------------------------------------------------
#define BB 16
#define SS 1024
#define EE 768
#define HH 12
#define DD 64
#define FF 3072
#define ROWS (BB * SS)          // 16384
#define QKV_N (3 * EE)          // 2304

// ---------------------------------------------------------------------------
// Scratch (device globals; no cudaMalloc allowed)
// ---------------------------------------------------------------------------
__device__ float g_h[ROWS * EE];        // LN output (reused for LN1 and LN2)
__device__ float g_qkv[ROWS * QKV_N];   // fused qkv projections [row][sec*768 + h*64 + d]
__device__ float g_o[ROWS * EE];        // attention output (heads concatenated)
__device__ float g_x1[ROWS * EE];       // residual after attention
__device__ float g_f1[ROWS * FF];       // gelu(h2 @ W1 + b1)
__device__ float g_f2[ROWS * EE];       // f1 @ W2 + b2
__device__ float g_wqkv[EE * QKV_N];    // packed qkv weights [e][sec*768 + h*64 + d]
__device__ float g_bqkv[QKV_N];         // packed qkv bias

// ---------------------------------------------------------------------------
// Pack Wq/Wk/Wv ([H,E,D] each) into row-major [E, 2304]; pack biases.
// ---------------------------------------------------------------------------
__global__ void pack_qkv_kernel(const float* __restrict__ Wq,
                                const float* __restrict__ Wk,
                                const float* __restrict__ Wv,
                                const float* __restrict__ bq,
                                const float* __restrict__ bk,
                                const float* __restrict__ bv) {
    int idx = blockIdx.x * blockDim.x + threadIdx.x;
    int total = EE * QKV_N;
    if (idx < total) {
        int e = idx / QKV_N;
        int j = idx % QKV_N;
        int sec = j / EE;       // 0=q 1=k 2=v
        int hd = j % EE;        // h*64 + d
        const float* W = (sec == 0) ? Wq : (sec == 1) ? Wk : Wv;
        // W[h, e, d] at ((hd>>6)*EE + e)*DD + (hd & 63)
        g_wqkv[idx] = W[((hd >> 6) * EE + e) * DD + (hd & 63)];
    }
    if (idx < QKV_N) {
        int sec = idx / EE;
        int hd = idx % EE;
        const float* bsrc = (sec == 0) ? bq : (sec == 1) ? bk : bv;
        g_bqkv[idx] = bsrc[hd];
    }
}

// ---------------------------------------------------------------------------
// Block reduce helper (256 threads)
// ---------------------------------------------------------------------------
__device__ __forceinline__ float block_reduce_sum_256(float v, float* sbuf) {
    int lane = threadIdx.x & 31;
    int wid  = threadIdx.x >> 5;
#pragma unroll
    for (int m = 16; m; m >>= 1) v += __shfl_xor_sync(0xffffffffu, v, m);
    if (lane == 0) sbuf[wid] = v;
    __syncthreads();
    if (wid == 0) {
        v = (lane < 8) ? sbuf[lane] : 0.f;
#pragma unroll
        for (int m = 4; m; m >>= 1) v += __shfl_xor_sync(0xffffffffu, v, m);
        if (lane == 0) sbuf[0] = v;
    }
    __syncthreads();
    float r = sbuf[0];
    __syncthreads();
    return r;
}

// ---------------------------------------------------------------------------
// LayerNorm: out = (res ? res + LN(in) : LN(in)). One block per row (E=768).
// ---------------------------------------------------------------------------
__global__ void __launch_bounds__(256) ln_kernel(const float* __restrict__ in,
                                                 const float* __restrict__ gam,
                                                 const float* __restrict__ bet,
                                                 const float* __restrict__ res,
                                                 float* __restrict__ out) {
    __shared__ float sbuf[8];
    size_t row = blockIdx.x;
    const float* x = in + row * EE;
    float s = 0.f;
    for (int i = threadIdx.x; i < EE; i += 256) s += x[i];
    float mu = block_reduce_sum_256(s, sbuf) * (1.f / EE);
    float v = 0.f;
    for (int i = threadIdx.x; i < EE; i += 256) {
        float d = x[i] - mu;
        v += d * d;
    }
    float var = block_reduce_sum_256(v, sbuf) * (1.f / EE);
    float rstd = rsqrtf(var + 1e-5f);
    for (int i = threadIdx.x; i < EE; i += 256) {
        float y = (x[i] - mu) * rstd * gam[i] + bet[i];
        if (res) y += res[row * EE + i];
        out[row * EE + i] = y;
    }
}

// ---------------------------------------------------------------------------
// SGEMM: C[M,N] = A[M,K] @ B[K,N] + bias[N], epilogue variants.
// 128x128 block tile, BK=16, 256 threads, 8x8 per thread.
// EPI: 0 = bias, 1 = bias + exact gelu, 2 = bias + residual add
// ---------------------------------------------------------------------------
template <int EPI>
__global__ void __launch_bounds__(256) sgemm_kernel(const float* __restrict__ A,
                                                    const float* __restrict__ B,
                                                    const float* __restrict__ bias,
                                                    const float* __restrict__ res,
                                                    float* __restrict__ C,
                                                    int M, int N, int K) {
    __shared__ float As[16][128];
    __shared__ float Bs[16][128];
    int tid = threadIdx.x;
    int tx = tid & 15, ty = tid >> 4;
    int bn = blockIdx.x * 128;
    int bm = blockIdx.y * 128;

    float acc[8][8];
#pragma unroll
    for (int i = 0; i < 8; i++)
#pragma unroll
        for (int j = 0; j < 8; j++) acc[i][j] = 0.f;

    const float* Aptr = A + (size_t)bm * K;
    const float* Bptr = B + bn;

    for (int kt = 0; kt < K; kt += 16) {
        // Load A tile (128x16), store transposed As[k][m]
#pragma unroll
        for (int i = 0; i < 2; i++) {
            int f = tid + i * 256;          // 0..511 float4 slots
            int r = f >> 2;                 // 0..127
            int c = (f & 3) << 2;           // 0,4,8,12
            float4 v = *(const float4*)(Aptr + (size_t)r * K + kt + c);
            As[c + 0][r] = v.x;
            As[c + 1][r] = v.y;
            As[c + 2][r] = v.z;
            As[c + 3][r] = v.w;
        }
        // Load B tile (16x128) directly
#pragma unroll
        for (int i = 0; i < 2; i++) {
            int f = tid + i * 256;
            int r = f >> 5;                 // 0..15
            int c = (f & 31) << 2;          // 0..124
            float4 v = *(const float4*)(Bptr + (size_t)(kt + r) * N + c);
            *(float4*)&Bs[r][c] = v;
        }
        __syncthreads();
#pragma unroll
        for (int k = 0; k < 16; k++) {
            float a[8], bb[8];
            *(float4*)&a[0]  = *(const float4*)&As[k][ty * 8];
            *(float4*)&a[4]  = *(const float4*)&As[k][ty * 8 + 4];
            *(float4*)&bb[0] = *(const float4*)&Bs[k][tx * 8];
            *(float4*)&bb[4] = *(const float4*)&Bs[k][tx * 8 + 4];
#pragma unroll
            for (int i = 0; i < 8; i++)
#pragma unroll
                for (int j = 0; j < 8; j++)
                    acc[i][j] = fmaf(a[i], bb[j], acc[i][j]);
        }
        __syncthreads();
    }

    int row0 = bm + ty * 8;
    int col0 = bn + tx * 8;
#pragma unroll
    for (int i = 0; i < 8; i++) {
#pragma unroll
        for (int j = 0; j < 8; j++) {
            float v = acc[i][j] + bias[col0 + j];
            if (EPI == 1) v = 0.5f * v * (1.0f + erff(v * 0.70710678118654752f));
            if (EPI == 2) v += res[(size_t)(row0 + i) * N + col0 + j];
            acc[i][j] = v;
        }
        float4 v0 = make_float4(acc[i][0], acc[i][1], acc[i][2], acc[i][3]);
        float4 v1 = make_float4(acc[i][4], acc[i][5], acc[i][6], acc[i][7]);
        *(float4*)(C + (size_t)(row0 + i) * N + col0)     = v0;
        *(float4*)(C + (size_t)(row0 + i) * N + col0 + 4) = v1;
    }
}

// ---------------------------------------------------------------------------
// Causal flash attention.
// grid = (S/64, B*H). block = 256 threads (16x16, 4x4 micro-tile).
// qkv layout: [row = b*S+s][sec*768 + h*64 + d], sec 0/1/2 = q/k/v.
// o layout:   [row][h*64 + d]   (heads concatenated)
// ---------------------------------------------------------------------------
#define AP 68   // padded smem stride

__global__ void __launch_bounds__(256) attn_kernel(const float* __restrict__ qkv,
                                                   float* __restrict__ o) {
    extern __shared__ float sm[];
    float* Qs = sm;                // [64][AP]  Qs[d][r]
    float* Ks = sm + 64 * AP;      // [64][AP]  Ks[d][t]
    float* Vs = sm + 2 * 64 * AP;  // [64][AP]  Vs[t][d]
    float* Ps = sm + 3 * 64 * AP;  // [64][AP]  Ps[t][r]

    int qt = blockIdx.x;
    int bh = blockIdx.y;
    int b = bh / HH, h = bh % HH;
    int tid = threadIdx.x;
    int tx = tid & 15, ty = tid >> 4;

    size_t base = (size_t)b * SS * QKV_N;
    int hoff = h * DD;

    // load Q tile (scaled by 1/sqrt(D)), transposed into Qs[d][r]
    for (int idx = tid; idx < 4096; idx += 256) {
        int r = idx >> 6, d = idx & 63;
        Qs[d * AP + r] = qkv[base + (size_t)(qt * 64 + r) * QKV_N + hoff + d] * 0.125f;
    }

    float m_i[4], l_i[4], acc[4][4];
#pragma unroll
    for (int i = 0; i < 4; i++) {
        m_i[i] = -1e30f;
        l_i[i] = 0.f;
#pragma unroll
        for (int j = 0; j < 4; j++) acc[i][j] = 0.f;
    }

    for (int kt = 0; kt <= qt; kt++) {
        __syncthreads();
        // load K (transposed) and V tiles
        for (int idx = tid; idx < 4096; idx += 256) {
            int r = idx >> 6, d = idx & 63;
            size_t off = base + (size_t)(kt * 64 + r) * QKV_N + hoff + d;
            Ks[d * AP + r] = qkv[off + EE];
            Vs[r * AP + d] = qkv[off + 2 * EE];
        }
        __syncthreads();

        // S = Q @ K^T   (rows = ty*4+i, key cols = tx*4+j)
        float s[4][4];
#pragma unroll
        for (int i = 0; i < 4; i++)
#pragma unroll
            for (int j = 0; j < 4; j++) s[i][j] = 0.f;
#pragma unroll 8
        for (int k = 0; k < 64; k++) {
            float a[4], bb[4];
#pragma unroll
            for (int i = 0; i < 4; i++) a[i] = Qs[k * AP + ty * 4 + i];
#pragma unroll
            for (int j = 0; j < 4; j++) bb[j] = Ks[k * AP + tx * 4 + j];
#pragma unroll
            for (int i = 0; i < 4; i++)
#pragma unroll
                for (int j = 0; j < 4; j++) s[i][j] = fmaf(a[i], bb[j], s[i][j]);
        }

        if (kt == qt) {  // causal mask on diagonal tile
#pragma unroll
            for (int i = 0; i < 4; i++)
#pragma unroll
                for (int j = 0; j < 4; j++)
                    if (tx * 4 + j > ty * 4 + i) s[i][j] = -1e30f;
        }

        // online softmax (row groups of 16 lanes share rows)
#pragma unroll
        for (int i = 0; i < 4; i++) {
            float mt = fmaxf(fmaxf(s[i][0], s[i][1]), fmaxf(s[i][2], s[i][3]));
#pragma unroll
            for (int off = 8; off; off >>= 1)
                mt = fmaxf(mt, __shfl_xor_sync(0xffffffffu, mt, off));
            float mnew = fmaxf(m_i[i], mt);
            float sc = __expf(m_i[i] - mnew);
            float rs = 0.f;
#pragma unroll
            for (int j = 0; j < 4; j++) {
                float p = __expf(s[i][j] - mnew);
                s[i][j] = p;
                rs += p;
            }
#pragma unroll
            for (int off = 8; off; off >>= 1)
                rs += __shfl_xor_sync(0xffffffffu, rs, off);
            l_i[i] = l_i[i] * sc + rs;
            m_i[i] = mnew;
#pragma unroll
            for (int j = 0; j < 4; j++) acc[i][j] *= sc;
        }

        // store P transposed: Ps[t][r]
#pragma unroll
        for (int i = 0; i < 4; i++)
#pragma unroll
            for (int j = 0; j < 4; j++)
                Ps[(tx * 4 + j) * AP + ty * 4 + i] = s[i][j];
        __syncthreads();

        // O += P @ V   (output cols = d = tx*4+j)
#pragma unroll 8
        for (int k = 0; k < 64; k++) {
            float a[4], bb[4];
#pragma unroll
            for (int i = 0; i < 4; i++) a[i] = Ps[k * AP + ty * 4 + i];
#pragma unroll
            for (int j = 0; j < 4; j++) bb[j] = Vs[k * AP + tx * 4 + j];
#pragma unroll
            for (int i = 0; i < 4; i++)
#pragma unroll
                for (int j = 0; j < 4; j++) acc[i][j] = fmaf(a[i], bb[j], acc[i][j]);
        }
    }

    // write O / l
#pragma unroll
    for (int i = 0; i < 4; i++) {
        float inv = 1.f / l_i[i];
        size_t row = (size_t)b * SS + qt * 64 + ty * 4 + i;
#pragma unroll
        for (int j = 0; j < 4; j++)
            o[row * EE + hoff + tx * 4 + j] = acc[i][j] * inv;
    }
}

// ---------------------------------------------------------------------------
// Launch
// ---------------------------------------------------------------------------
extern "C" void kernel_launch(void* const* d_in, const int* in_sizes, int n_in,
                              void* d_out, int out_size) {
    const float* x     = (const float*)d_in[0];
    const float* Wq    = (const float*)d_in[1];
    const float* bq    = (const float*)d_in[2];
    const float* Wk    = (const float*)d_in[3];
    const float* bk    = (const float*)d_in[4];
    const float* Wv    = (const float*)d_in[5];
    const float* bv    = (const float*)d_in[6];
    const float* Wp    = (const float*)d_in[7];
    const float* bp    = (const float*)d_in[8];
    const float* ln1_g = (const float*)d_in[9];
    const float* ln1_b = (const float*)d_in[10];
    const float* ln2_g = (const float*)d_in[11];
    const float* ln2_b = (const float*)d_in[12];
    const float* W1    = (const float*)d_in[13];
    const float* b1    = (const float*)d_in[14];
    const float* W2    = (const float*)d_in[15];
    const float* b2    = (const float*)d_in[16];
    const float* lnf_g = (const float*)d_in[17];
    const float* lnf_b = (const float*)d_in[18];
    float* out = (float*)d_out;

    float *p_h, *p_qkv, *p_o, *p_x1, *p_f1, *p_f2, *p_wqkv, *p_bqkv;
    cudaGetSymbolAddress((void**)&p_h, g_h);
    cudaGetSymbolAddress((void**)&p_qkv, g_qkv);
    cudaGetSymbolAddress((void**)&p_o, g_o);
    cudaGetSymbolAddress((void**)&p_x1, g_x1);
    cudaGetSymbolAddress((void**)&p_f1, g_f1);
    cudaGetSymbolAddress((void**)&p_f2, g_f2);
    cudaGetSymbolAddress((void**)&p_wqkv, g_wqkv);
    cudaGetSymbolAddress((void**)&p_bqkv, g_bqkv);

    int attn_smem = 4 * 64 * AP * (int)sizeof(float);  // 69632 B
    cudaFuncSetAttribute(attn_kernel, cudaFuncAttributeMaxDynamicSharedMemorySize,
                         attn_smem);

    // 1. pack qkv weights + biases
    {
        int total = EE * QKV_N;
        pack_qkv_kernel<<<(total + 255) / 256, 256>>>(Wq, Wk, Wv, bq, bk, bv);
    }

    // 2. LN1: h = LN(x)
    ln_kernel<<<ROWS, 256>>>(x, ln1_g, ln1_b, nullptr, p_h);

    // 3. qkv = h @ Wqkv + bqkv      [16384, 2304]
    sgemm_kernel<0><<<dim3(QKV_N / 128, ROWS / 128), 256>>>(
        p_h, p_wqkv, p_bqkv, nullptr, p_qkv, ROWS, QKV_N, EE);

    // 4. attention -> o [16384, 768]
    attn_kernel<<<dim3(SS / 64, BB * HH), 256, attn_smem>>>(p_qkv, p_o);

    // 5. x1 = x + o @ Wp + bp
    sgemm_kernel<2><<<dim3(EE / 128, ROWS / 128), 256>>>(
        p_o, Wp, bp, x, p_x1, ROWS, EE, EE);

    // 6. LN2: h2 = LN(x1)  (reuse g_h)
    ln_kernel<<<ROWS, 256>>>(p_x1, ln2_g, ln2_b, nullptr, p_h);

    // 7. f1 = gelu(h2 @ W1 + b1)   [16384, 3072]
    sgemm_kernel<1><<<dim3(FF / 128, ROWS / 128), 256>>>(
        p_h, W1, b1, nullptr, p_f1, ROWS, FF, EE);

    // 8. f2 = f1 @ W2 + b2         [16384, 768]
    sgemm_kernel<0><<<dim3(EE / 128, ROWS / 128), 256>>>(
        p_f1, W2, b2, nullptr, p_f2, ROWS, EE, FF);

    // 9. out = x1 + LN(f2)
    ln_kernel<<<ROWS, 256>>>(p_f2, lnf_g, lnf_b, p_x1, out);
}